// round 3
// baseline (speedup 1.0000x reference)
#include <cuda_runtime.h>

#define NHEADS 8
#define HDIM   64
#define QLEN   16
#define HIDDEN 512
#define BLKSZ  16
#define NLOGICAL 2048
#define NSPLIT 128
#define BLOCKS_PER_SPLIT (NLOGICAL / NSPLIT)   // 16

// scratch (no cudaMalloc allowed) — 16B-aligned for float4 access
__device__ __align__(16) float g_q [NHEADS * QLEN * HDIM];
__device__ __align__(16) float g_pm[NHEADS * NSPLIT * QLEN];
__device__ __align__(16) float g_pl[NHEADS * NSPLIT * QLEN];
__device__ __align__(16) float g_po[NHEADS * NSPLIT * QLEN * HDIM];
__device__ __align__(16) float g_ao[QLEN * HIDDEN];
__device__ int g_bt[NLOGICAL];   // normalized int32 block table

// ---------------------------------------------------------------------------
// Kernel 0: normalize the block table to int32, auto-detecting whether the
// buffer holds int32 or little-endian int64 indices. Single CTA.
// Safe: reads only 2048 x 4B = 8192 B, <= buffer size under both dtypes.
// ---------------------------------------------------------------------------
__global__ __launch_bounds__(1024) void btnorm_kernel(const int* __restrict__ bt_raw) {
    __shared__ int s_odd_nonzero;
    if (threadIdx.x == 0) s_odd_nonzero = 0;
    __syncthreads();

    // If values are int64 LE in [0, 4096), every odd 32-bit word is 0.
    int t = threadIdx.x;
    int v0 = bt_raw[2 * t];        // words 0..2047
    int v1 = bt_raw[2 * t + 1];
    if (v1 != 0) atomicOr(&s_odd_nonzero, 1);
    __syncthreads();
    bool is32 = (s_odd_nonzero != 0);

    if (is32) {
        // buffer is 2048 int32s: words 2t and 2t+1 are entries 2t, 2t+1
        g_bt[2 * t]     = v0 & 4095;
        g_bt[2 * t + 1] = v1 & 4095;
    } else {
        // buffer is 2048 int64s: entry i is word 2i (low half)
        g_bt[t]        = v0 & 4095;                     // entries 0..1023 (word 2t)... 
    }
    __syncthreads();
    if (!is32) {
        // entries 1024..2047 live at words 2048..4094 (even words)
        g_bt[1024 + t] = bt_raw[2048 + 2 * t] & 4095;
    }
}

// ---------------------------------------------------------------------------
// Kernel 1: q = (hs @ Wq^T + bq) * 0.125, rearranged to [h][s][d]
// ---------------------------------------------------------------------------
__global__ __launch_bounds__(256) void qproj_kernel(const float* __restrict__ hs,
                                                    const float* __restrict__ Wq,
                                                    const float* __restrict__ bq) {
    int gw   = (blockIdx.x * 256 + threadIdx.x) >> 5;   // 0..8191
    int lane = threadIdx.x & 31;
    int s = gw >> 9;          // 0..15
    int j = gw & 511;         // 0..511
    const float4* x = (const float4*)(hs + s * HIDDEN);
    const float4* w = (const float4*)(Wq + j * HIDDEN);
    float acc = 0.f;
#pragma unroll
    for (int it = 0; it < 4; it++) {
        float4 a = x[lane + it * 32];
        float4 b = w[lane + it * 32];
        acc += a.x * b.x + a.y * b.y + a.z * b.z + a.w * b.w;
    }
#pragma unroll
    for (int off = 16; off; off >>= 1) acc += __shfl_xor_sync(0xffffffffu, acc, off);
    if (lane == 0) {
        float v = (acc + bq[j]) * 0.125f;  // fold 1/sqrt(64)
        int h = j >> 6, d = j & 63;
        g_q[(h * QLEN + s) * HDIM + d] = v;
    }
}

// ---------------------------------------------------------------------------
// Kernel 2: split-KV flash attention over the paged gather.
// grid = (NSPLIT, NHEADS), 256 threads; 16 logical KV blocks per CTA.
// ---------------------------------------------------------------------------
__global__ __launch_bounds__(256) void attn_kernel(const float* __restrict__ kc,
                                                   const float* __restrict__ vc) {
    const int h   = blockIdx.y;
    const int sp  = blockIdx.x;
    const int tid = threadIdx.x;
    const int qi  = tid >> 4;
    const int li  = tid & 15;

    __shared__ __align__(16) float q_s[16 * 68];
    __shared__ __align__(16) float Ks [16 * 68];
    __shared__ __align__(16) float Vs [16 * 68];
    __shared__ __align__(16) float p_s[16 * 17];
    __shared__ float m_s[16], l_s[16], a_s[16];

    // load q tile (already scaled)
    {
        float4 qv = ((const float4*)(g_q + h * QLEN * HDIM))[tid];
        ((float4*)(q_s + qi * 68))[li] = qv;
    }
    if (tid < 16) { m_s[tid] = -1e30f; l_s[tid] = 0.f; }

    float4 o = make_float4(0.f, 0.f, 0.f, 0.f);
    __syncthreads();

    const int lb0 = sp * BLOCKS_PER_SPLIT;
    for (int b = 0; b < BLOCKS_PER_SPLIT; b++) {
        long long blk = (long long)g_bt[lb0 + b];
        const float* kbas = kc + blk * (NHEADS * BLKSZ * HDIM) + h * (BLKSZ * HDIM);
        const float* vbas = vc + blk * (NHEADS * BLKSZ * HDIM) + h * (BLKSZ * HDIM);
        float4 kv = ((const float4*)kbas)[tid];   // issue global loads before barrier
        float4 vv = ((const float4*)vbas)[tid];

        __syncthreads();                           // prev iter done reading Ks/Vs
        ((float4*)(Ks + qi * 68))[li] = kv;        // row = tid>>4, col4 = li
        ((float4*)(Vs + qi * 68))[li] = vv;
        __syncthreads();

        // ---- scores: s(qi, ki=li) = q[qi] . k[ki]
        float s = 0.f;
        const float4* qr = (const float4*)(q_s + qi * 68);
        const float4* kr = (const float4*)(Ks  + li * 68);
#pragma unroll
        for (int i = 0; i < 16; i++) {
            float4 a = qr[i], k4 = kr[i];
            s += a.x * k4.x + a.y * k4.y + a.z * k4.z + a.w * k4.w;
        }
        // 16-lane row reductions (rows never cross a warp boundary)
        float mx = s;
#pragma unroll
        for (int off = 8; off; off >>= 1) mx = fmaxf(mx, __shfl_xor_sync(0xffffffffu, mx, off));
        float m_old = m_s[qi];
        float m_new = fmaxf(m_old, mx);
        float p  = __expf(s - m_new);
        float su = p;
#pragma unroll
        for (int off = 8; off; off >>= 1) su += __shfl_xor_sync(0xffffffffu, su, off);
        p_s[qi * 17 + li] = p;
        if (li == 0) {
            float alpha = __expf(m_old - m_new);
            a_s[qi] = alpha;
            l_s[qi] = l_s[qi] * alpha + su;
            m_s[qi] = m_new;
        }
        __syncwarp();   // p_s / a_s producers & consumers share a warp

        // ---- PV: thread (qi, dg=li) owns o[qi][4*li .. 4*li+3]
        float alpha = a_s[qi];
        o.x *= alpha; o.y *= alpha; o.z *= alpha; o.w *= alpha;
#pragma unroll
        for (int k2 = 0; k2 < 16; k2++) {
            float p2  = p_s[qi * 17 + k2];
            float4 v4 = ((const float4*)(Vs + k2 * 68))[li];
            o.x += p2 * v4.x; o.y += p2 * v4.y; o.z += p2 * v4.z; o.w += p2 * v4.w;
        }
    }

    // write partials
    int base = ((h * NSPLIT + sp) * QLEN + qi) * HDIM;
    ((float4*)(g_po + base))[li] = o;
    __syncthreads();   // m_s/l_s written by other warps
    if (tid < 16) {
        g_pm[(h * NSPLIT + sp) * QLEN + tid] = m_s[tid];
        g_pl[(h * NSPLIT + sp) * QLEN + tid] = l_s[tid];
    }
}

// ---------------------------------------------------------------------------
// Kernel 3: combine NSPLIT partials per (h, qi) with log-sum-exp weights.
// ---------------------------------------------------------------------------
__global__ __launch_bounds__(128) void reduce_kernel() {
    int h  = blockIdx.x >> 4;
    int qi = blockIdx.x & 15;
    int t  = threadIdx.x;  // split index

    __shared__ float red[NSPLIT];
    __shared__ float wgt[NSPLIT];

    float m = g_pm[(h * NSPLIT + t) * QLEN + qi];
    float l = g_pl[(h * NSPLIT + t) * QLEN + qi];

    red[t] = m; __syncthreads();
    for (int off = 64; off; off >>= 1) {
        if (t < off) red[t] = fmaxf(red[t], red[t + off]);
        __syncthreads();
    }
    float mstar = red[0];
    __syncthreads();

    float e = __expf(m - mstar);
    red[t] = l * e; __syncthreads();
    for (int off = 64; off; off >>= 1) {
        if (t < off) red[t] += red[t + off];
        __syncthreads();
    }
    float L = red[0];
    __syncthreads();

    wgt[t] = e / L;
    __syncthreads();

    if (t < HDIM) {
        float acc = 0.f;
        for (int sp = 0; sp < NSPLIT; sp++)
            acc += wgt[sp] * g_po[((h * NSPLIT + sp) * QLEN + qi) * HDIM + t];
        g_ao[qi * HIDDEN + h * HDIM + t] = acc;
    }
}

// ---------------------------------------------------------------------------
// Kernel 4: out = g_ao @ Wo^T + bo  (warp-per-output)
// ---------------------------------------------------------------------------
__global__ __launch_bounds__(256) void oproj_kernel(const float* __restrict__ Wo,
                                                    const float* __restrict__ bo,
                                                    float* __restrict__ out) {
    int gw   = (blockIdx.x * 256 + threadIdx.x) >> 5;
    int lane = threadIdx.x & 31;
    int s = gw >> 9;
    int j = gw & 511;
    const float4* x = (const float4*)(g_ao + s * HIDDEN);
    const float4* w = (const float4*)(Wo + j * HIDDEN);
    float acc = 0.f;
#pragma unroll
    for (int it = 0; it < 4; it++) {
        float4 a = x[lane + it * 32];
        float4 b = w[lane + it * 32];
        acc += a.x * b.x + a.y * b.y + a.z * b.z + a.w * b.w;
    }
#pragma unroll
    for (int off = 16; off; off >>= 1) acc += __shfl_xor_sync(0xffffffffu, acc, off);
    if (lane == 0) out[s * HIDDEN + j] = acc + bo[j];
}

// ---------------------------------------------------------------------------
extern "C" void kernel_launch(void* const* d_in, const int* in_sizes, int n_in,
                              void* d_out, int out_size) {
    // Identify inputs by element count (robust to metadata ordering, as long
    // as same-size tensors keep their relative order: K before V, Wq before
    // Wo, bq before bo — matching the reference setup_inputs order).
    const float *hs = 0, *kc = 0, *vc = 0, *Wq = 0, *bq = 0, *Wo = 0, *bo = 0;
    const int* bt_raw = 0;
    for (int i = 0; i < n_in; i++) {
        switch (in_sizes[i]) {
            case QLEN * HIDDEN:                      // 8192
                hs = (const float*)d_in[i]; break;
            case 4096 * NHEADS * BLKSZ * HDIM:       // 33554432
                if (!kc) kc = (const float*)d_in[i];
                else     vc = (const float*)d_in[i];
                break;
            case HIDDEN * HIDDEN:                    // 262144
                if (!Wq) Wq = (const float*)d_in[i];
                else     Wo = (const float*)d_in[i];
                break;
            case HIDDEN:                             // 512
                if (!bq) bq = (const float*)d_in[i];
                else     bo = (const float*)d_in[i];
                break;
            case NLOGICAL:                           // 2048
                bt_raw = (const int*)d_in[i]; break;
            default: break;
        }
    }
    float* out = (float*)d_out;                      // [1,16,512]

    btnorm_kernel<<<1, 1024>>>(bt_raw);
    qproj_kernel<<<1024, 256>>>(hs, Wq, bq);
    dim3 g(NSPLIT, NHEADS);
    attn_kernel<<<g, 256>>>(kc, vc);
    reduce_kernel<<<NHEADS * QLEN, NSPLIT>>>();
    oproj_kernel<<<1024, 256>>>(Wo, bo, out);
}

// round 4
// speedup vs baseline: 1.5986x; 1.5986x over previous
#include <cuda_runtime.h>

#define NHEADS 8
#define HDIM   64
#define QLEN   16
#define HIDDEN 512
#define BLKSZ  16
#define NLOGICAL 2048
#define NSPLIT 128
#define BPS (NLOGICAL / NSPLIT)   // 16 blocks per split

typedef unsigned long long ull;

// scratch (no cudaMalloc allowed)
__device__ __align__(16) float g_q [NHEADS * QLEN * HDIM];
__device__ __align__(16) float g_pl[NHEADS * NSPLIT * QLEN];
__device__ __align__(16) float g_po[NHEADS * NSPLIT * QLEN * HDIM];
__device__ __align__(16) float g_ao[QLEN * HIDDEN];
__device__ int g_bt[NLOGICAL];

// ---- packed f32x2 helpers (ptxas won't emit FFMA2 from C++) -------------
__device__ __forceinline__ ull pk2(float lo, float hi) {
    ull r; asm("mov.b64 %0,{%1,%2};" : "=l"(r) : "f"(lo), "f"(hi)); return r;
}
__device__ __forceinline__ void upk2(ull p, float& lo, float& hi) {
    asm("mov.b64 {%0,%1},%2;" : "=f"(lo), "=f"(hi) : "l"(p));
}
__device__ __forceinline__ ull fma2(ull a, ull b, ull c) {
    ull d; asm("fma.rn.f32x2 %0,%1,%2,%3;" : "=l"(d) : "l"(a), "l"(b), "l"(c)); return d;
}

// ---------------------------------------------------------------------------
// Kernel 0: normalize block table (int32 vs int64 LE auto-detect). 1 CTA.
// ---------------------------------------------------------------------------
__global__ __launch_bounds__(1024) void btnorm_kernel(const int* __restrict__ bt_raw) {
    __shared__ int s_odd_nonzero;
    if (threadIdx.x == 0) s_odd_nonzero = 0;
    __syncthreads();
    int t = threadIdx.x;
    int v0 = bt_raw[2 * t];
    int v1 = bt_raw[2 * t + 1];
    if (v1 != 0) atomicOr(&s_odd_nonzero, 1);
    __syncthreads();
    bool is32 = (s_odd_nonzero != 0);
    if (is32) {
        g_bt[2 * t]     = v0 & 4095;
        g_bt[2 * t + 1] = v1 & 4095;
    } else {
        g_bt[t] = v0 & 4095;
    }
    __syncthreads();
    if (!is32) g_bt[1024 + t] = bt_raw[2048 + 2 * t] & 4095;
}

// ---------------------------------------------------------------------------
// Kernel 1: q = (hs @ Wq^T + bq) * 0.125 -> g_q[h][s][d]
// ---------------------------------------------------------------------------
__global__ __launch_bounds__(256) void qproj_kernel(const float* __restrict__ hs,
                                                    const float* __restrict__ Wq,
                                                    const float* __restrict__ bq) {
    int gw   = (blockIdx.x * 256 + threadIdx.x) >> 5;
    int lane = threadIdx.x & 31;
    int s = gw >> 9;
    int j = gw & 511;
    const float4* x = (const float4*)(hs + s * HIDDEN);
    const float4* w = (const float4*)(Wq + j * HIDDEN);
    float acc = 0.f;
#pragma unroll
    for (int it = 0; it < 4; it++) {
        float4 a = x[lane + it * 32];
        float4 b = w[lane + it * 32];
        acc += a.x * b.x + a.y * b.y + a.z * b.z + a.w * b.w;
    }
#pragma unroll
    for (int off = 16; off; off >>= 1) acc += __shfl_xor_sync(0xffffffffu, acc, off);
    if (lane == 0) {
        float v = (acc + bq[j]) * 0.125f;
        int h = j >> 6, d = j & 63;
        g_q[(h * QLEN + s) * HDIM + d] = v;
    }
}

// ---------------------------------------------------------------------------
// Kernel 2: split-KV attention, no-max softmax, f32x2 packed math.
// grid (NSPLIT, NHEADS), 128 threads. Thread (grp=tid>>4, col=tid&15)
// handles q rows {grp, grp+8}; col = ki in score phase, d-quad in PV phase.
// Double-buffered K/V tiles; one __syncthreads per tile.
// ---------------------------------------------------------------------------
__global__ __launch_bounds__(128) void attn_kernel(const float* __restrict__ kc,
                                                   const float* __restrict__ vc) {
    const int h   = blockIdx.y;
    const int sp  = blockIdx.x;
    const int tid = threadIdx.x;
    const int col = tid & 15;
    const int grp = tid >> 4;     // 0..7

    __shared__ __align__(16) float QS[16 * 68];
    __shared__ __align__(16) float KS[2][16 * 68];
    __shared__ __align__(16) float VS[2][16 * 68];
    __shared__ float PS[16 * 17];

    // q tile -> smem (2 float4 per thread)
    {
        const float4* qg = (const float4*)(g_q + h * QLEN * HDIM);
#pragma unroll
        for (int j = 0; j < 2; j++) {
            int e = tid + j * 128;
            ((float4*)(QS + (e >> 4) * 68))[e & 15] = qg[e];
        }
    }

    const int lb0 = sp * BPS;
    const int r0 = tid >> 4, c0 = tid & 15;
    const int e1 = tid + 128, r1 = e1 >> 4, c1 = e1 & 15;

    float4 kr0, kr1, vr0, vr1;
    {   // prologue: tile 0
        long long blk = (long long)g_bt[lb0];
        const float4* kb = (const float4*)(kc + blk * (NHEADS * BLKSZ * HDIM) + h * (BLKSZ * HDIM));
        const float4* vb = (const float4*)(vc + blk * (NHEADS * BLKSZ * HDIM) + h * (BLKSZ * HDIM));
        kr0 = kb[tid]; kr1 = kb[tid + 128];
        vr0 = vb[tid]; vr1 = vb[tid + 128];
        ((float4*)(KS[0] + r0 * 68))[c0] = kr0; ((float4*)(KS[0] + r1 * 68))[c1] = kr1;
        ((float4*)(VS[0] + r0 * 68))[c0] = vr0; ((float4*)(VS[0] + r1 * 68))[c1] = vr1;
    }

    float l0 = 0.f, l1 = 0.f;
    ull oxy0 = 0, ozw0 = 0, oxy1 = 0, ozw1 = 0;   // packed accumulators

    for (int b = 0; b < BPS; b++) {
        __syncthreads();   // tile b visible; buffers from b-1 free
        const int cur = b & 1;

        if (b + 1 < BPS) {  // prefetch tile b+1 into registers
            long long blk = (long long)g_bt[lb0 + b + 1];
            const float4* kb = (const float4*)(kc + blk * (NHEADS * BLKSZ * HDIM) + h * (BLKSZ * HDIM));
            const float4* vb = (const float4*)(vc + blk * (NHEADS * BLKSZ * HDIM) + h * (BLKSZ * HDIM));
            kr0 = kb[tid]; kr1 = kb[tid + 128];
            vr0 = vb[tid]; vr1 = vb[tid + 128];
        }

        // ---- scores for (grp,col) and (grp+8,col)
        ull a0 = 0, b0 = 0, a1 = 0, b1 = 0;
        const float* kp  = KS[cur] + col * 68;
        const float* q0p = QS + grp * 68;
        const float* q1p = QS + (grp + 8) * 68;
#pragma unroll
        for (int i = 0; i < 16; i++) {
            float4 k4  = ((const float4*)kp )[i];
            float4 q04 = ((const float4*)q0p)[i];
            float4 q14 = ((const float4*)q1p)[i];
            ull kxy = pk2(k4.x, k4.y), kzw = pk2(k4.z, k4.w);
            a0 = fma2(pk2(q04.x, q04.y), kxy, a0);
            b0 = fma2(pk2(q04.z, q04.w), kzw, b0);
            a1 = fma2(pk2(q14.x, q14.y), kxy, a1);
            b1 = fma2(pk2(q14.z, q14.w), kzw, b1);
        }
        float x, y, z, w, s0, s1;
        upk2(a0, x, y); upk2(b0, z, w); s0 = (x + y) + (z + w);
        upk2(a1, x, y); upk2(b1, z, w); s1 = (x + y) + (z + w);

        float p0 = __expf(s0), p1 = __expf(s1);
        PS[grp * 17 + col]       = p0;
        PS[(grp + 8) * 17 + col] = p1;
        float t0 = p0, t1 = p1;
#pragma unroll
        for (int off = 8; off; off >>= 1) {
            t0 += __shfl_xor_sync(0xffffffffu, t0, off);
            t1 += __shfl_xor_sync(0xffffffffu, t1, off);
        }
        l0 += t0; l1 += t1;
        __syncwarp();   // PS producers/consumers share the warp

        // ---- PV: o rows {grp, grp+8}, d-quad col
        const float* vbase = VS[cur];
#pragma unroll
        for (int k2 = 0; k2 < 16; k2++) {
            float  p0k = PS[grp * 17 + k2];
            float  p1k = PS[(grp + 8) * 17 + k2];
            float4 v4  = ((const float4*)(vbase + k2 * 68))[col];
            ull vxy = pk2(v4.x, v4.y), vzw = pk2(v4.z, v4.w);
            ull pp0 = pk2(p0k, p0k),   pp1 = pk2(p1k, p1k);
            oxy0 = fma2(pp0, vxy, oxy0); ozw0 = fma2(pp0, vzw, ozw0);
            oxy1 = fma2(pp1, vxy, oxy1); ozw1 = fma2(pp1, vzw, ozw1);
        }

        if (b + 1 < BPS) {  // stash tile b+1 (other buffer; safe w/o barrier)
            const int nxt = cur ^ 1;
            ((float4*)(KS[nxt] + r0 * 68))[c0] = kr0; ((float4*)(KS[nxt] + r1 * 68))[c1] = kr1;
            ((float4*)(VS[nxt] + r0 * 68))[c0] = vr0; ((float4*)(VS[nxt] + r1 * 68))[c1] = vr1;
        }
    }

    // write partials (unnormalized sums; combination is additive)
    float4 o;
    upk2(oxy0, o.x, o.y); upk2(ozw0, o.z, o.w);
    ((float4*)(g_po + ((h * NSPLIT + sp) * QLEN + grp) * HDIM))[col] = o;
    upk2(oxy1, o.x, o.y); upk2(ozw1, o.z, o.w);
    ((float4*)(g_po + ((h * NSPLIT + sp) * QLEN + grp + 8) * HDIM))[col] = o;
    if (col == 0) {
        g_pl[(h * NSPLIT + sp) * QLEN + grp]     = l0;
        g_pl[(h * NSPLIT + sp) * QLEN + grp + 8] = l1;
    }
}

// ---------------------------------------------------------------------------
// Kernel 3: plain additive combine. grid 128 = (h,qi), 256 threads.
// ---------------------------------------------------------------------------
__global__ __launch_bounds__(256) void reduce_kernel() {
    int h = blockIdx.x >> 4, qi = blockIdx.x & 15, t = threadIdx.x;
    __shared__ float pacc[4][64];
    __shared__ float lsh[256];

    float lv = (t < NSPLIT) ? g_pl[(h * NSPLIT + t) * QLEN + qi] : 0.f;
    lsh[t] = lv; __syncthreads();
    for (int off = 128; off; off >>= 1) {
        if (t < off) lsh[t] += lsh[t + off];
        __syncthreads();
    }

    int d = t & 63, ch = t >> 6;
    float acc = 0.f;
#pragma unroll 8
    for (int sp = ch * 32; sp < ch * 32 + 32; sp++)
        acc += g_po[((h * NSPLIT + sp) * QLEN + qi) * HDIM + d];
    pacc[ch][d] = acc;
    __syncthreads();
    if (t < 64) {
        float tot = pacc[0][t] + pacc[1][t] + pacc[2][t] + pacc[3][t];
        g_ao[qi * HIDDEN + h * HDIM + t] = tot / lsh[0];
    }
}

// ---------------------------------------------------------------------------
// Kernel 4: out = g_ao @ Wo^T + bo (warp-per-output)
// ---------------------------------------------------------------------------
__global__ __launch_bounds__(256) void oproj_kernel(const float* __restrict__ Wo,
                                                    const float* __restrict__ bo,
                                                    float* __restrict__ out) {
    int gw   = (blockIdx.x * 256 + threadIdx.x) >> 5;
    int lane = threadIdx.x & 31;
    int s = gw >> 9;
    int j = gw & 511;
    const float4* x = (const float4*)(g_ao + s * HIDDEN);
    const float4* w = (const float4*)(Wo + j * HIDDEN);
    float acc = 0.f;
#pragma unroll
    for (int it = 0; it < 4; it++) {
        float4 a = x[lane + it * 32];
        float4 b = w[lane + it * 32];
        acc += a.x * b.x + a.y * b.y + a.z * b.z + a.w * b.w;
    }
#pragma unroll
    for (int off = 16; off; off >>= 1) acc += __shfl_xor_sync(0xffffffffu, acc, off);
    if (lane == 0) out[s * HIDDEN + j] = acc + bo[j];
}

// ---------------------------------------------------------------------------
extern "C" void kernel_launch(void* const* d_in, const int* in_sizes, int n_in,
                              void* d_out, int out_size) {
    const float *hs = 0, *kc = 0, *vc = 0, *Wq = 0, *bq = 0, *Wo = 0, *bo = 0;
    const int* bt_raw = 0;
    for (int i = 0; i < n_in; i++) {
        switch (in_sizes[i]) {
            case QLEN * HIDDEN:                 hs = (const float*)d_in[i]; break;
            case 4096 * NHEADS * BLKSZ * HDIM:
                if (!kc) kc = (const float*)d_in[i];
                else     vc = (const float*)d_in[i];
                break;
            case HIDDEN * HIDDEN:
                if (!Wq) Wq = (const float*)d_in[i];
                else     Wo = (const float*)d_in[i];
                break;
            case HIDDEN:
                if (!bq) bq = (const float*)d_in[i];
                else     bo = (const float*)d_in[i];
                break;
            case NLOGICAL:                      bt_raw = (const int*)d_in[i]; break;
            default: break;
        }
    }
    float* out = (float*)d_out;

    btnorm_kernel<<<1, 1024>>>(bt_raw);
    qproj_kernel<<<1024, 256>>>(hs, Wq, bq);
    dim3 g(NSPLIT, NHEADS);
    attn_kernel<<<g, 128>>>(kc, vc);
    reduce_kernel<<<NHEADS * QLEN, 256>>>();
    oproj_kernel<<<1024, 256>>>(Wo, bo, out);
}

// round 5
// speedup vs baseline: 1.6100x; 1.0071x over previous
#include <cuda_runtime.h>

#define NHEADS 8
#define HDIM   64
#define QLEN   16
#define HIDDEN 512
#define BLKSZ  16
#define NLOGICAL 2048
#define NSPLIT 128
#define BPS (NLOGICAL / NSPLIT)   // 16 blocks per split

typedef unsigned long long ull;

// scratch (no cudaMalloc allowed)
__device__ __align__(16) float g_q [NHEADS * QLEN * HDIM];
__device__ __align__(16) float g_pl[NHEADS * NSPLIT * QLEN];
__device__ __align__(16) float g_po[NHEADS * NSPLIT * QLEN * HDIM];
__device__ __align__(16) float g_ao[QLEN * HIDDEN];
__device__ int g_bt[NLOGICAL];

// ---- packed f32x2 helpers ------------------------------------------------
__device__ __forceinline__ ull pk2(float lo, float hi) {
    ull r; asm("mov.b64 %0,{%1,%2};" : "=l"(r) : "f"(lo), "f"(hi)); return r;
}
__device__ __forceinline__ void upk2(ull p, float& lo, float& hi) {
    asm("mov.b64 {%0,%1},%2;" : "=f"(lo), "=f"(hi) : "l"(p));
}
__device__ __forceinline__ ull fma2(ull a, ull b, ull c) {
    ull d; asm("fma.rn.f32x2 %0,%1,%2,%3;" : "=l"(d) : "l"(a), "l"(b), "l"(c)); return d;
}

// ---------------------------------------------------------------------------
// Kernel 0: normalize block table (int32 vs int64 LE auto-detect). 1 CTA.
// ---------------------------------------------------------------------------
__global__ __launch_bounds__(1024) void btnorm_kernel(const int* __restrict__ bt_raw) {
    __shared__ int s_odd_nonzero;
    if (threadIdx.x == 0) s_odd_nonzero = 0;
    __syncthreads();
    int t = threadIdx.x;
    int v0 = bt_raw[2 * t];
    int v1 = bt_raw[2 * t + 1];
    if (v1 != 0) atomicOr(&s_odd_nonzero, 1);
    __syncthreads();
    bool is32 = (s_odd_nonzero != 0);
    if (is32) {
        g_bt[2 * t]     = v0 & 4095;
        g_bt[2 * t + 1] = v1 & 4095;
    } else {
        g_bt[t] = v0 & 4095;
    }
    __syncthreads();
    if (!is32) g_bt[1024 + t] = bt_raw[2048 + 2 * t] & 4095;
}

// ---------------------------------------------------------------------------
// Kernel 1: q = (hs @ Wq^T + bq) * 0.125 -> g_q[h][s][d]
// ---------------------------------------------------------------------------
__global__ __launch_bounds__(256) void qproj_kernel(const float* __restrict__ hs,
                                                    const float* __restrict__ Wq,
                                                    const float* __restrict__ bq) {
    int gw   = (blockIdx.x * 256 + threadIdx.x) >> 5;
    int lane = threadIdx.x & 31;
    int s = gw >> 9;
    int j = gw & 511;
    const float4* x = (const float4*)(hs + s * HIDDEN);
    const float4* w = (const float4*)(Wq + j * HIDDEN);
    float acc = 0.f;
#pragma unroll
    for (int it = 0; it < 4; it++) {
        float4 a = x[lane + it * 32];
        float4 b = w[lane + it * 32];
        acc += a.x * b.x + a.y * b.y + a.z * b.z + a.w * b.w;
    }
#pragma unroll
    for (int off = 16; off; off >>= 1) acc += __shfl_xor_sync(0xffffffffu, acc, off);
    if (lane == 0) {
        float v = (acc + bq[j]) * 0.125f;
        int h = j >> 6, d = j & 63;
        g_q[(h * QLEN + s) * HDIM + d] = v;
    }
}

// ---------------------------------------------------------------------------
// Kernel 2: split-KV attention, no-max softmax, pure packed-f32x2 datapath.
// grid (NSPLIT, NHEADS), 128 threads. Thread (grp=tid>>4, col=tid&15)
// owns q rows {grp, grp+8}; col = ki in score phase, d-quad in PV phase.
// smem read as ulonglong2 so FFMA2 operands need no register packing.
// ---------------------------------------------------------------------------
__global__ __launch_bounds__(128) void attn_kernel(const float* __restrict__ kc,
                                                   const float* __restrict__ vc) {
    const int h   = blockIdx.y;
    const int sp  = blockIdx.x;
    const int tid = threadIdx.x;
    const int col = tid & 15;
    const int grp = tid >> 4;     // 0..7

    __shared__ __align__(16) float QS[16 * 68];
    __shared__ __align__(16) float KS[2][16 * 68];
    __shared__ __align__(16) float VS[2][16 * 68];
    __shared__ __align__(16) ull   PS2[16 * 17];   // pre-duplicated exp(s) pairs

    // q tile -> smem
    {
        const float4* qg = (const float4*)(g_q + h * QLEN * HDIM);
#pragma unroll
        for (int j = 0; j < 2; j++) {
            int e = tid + j * 128;
            ((float4*)(QS + (e >> 4) * 68))[e & 15] = qg[e];
        }
    }

    const int lb0 = sp * BPS;
    const long long headoff = (long long)h * (BLKSZ * HDIM);
    const int r0 = tid >> 4, c0 = tid & 15;
    const int e1 = tid + 128, r1 = e1 >> 4, c1 = e1 & 15;

    float4 kr0, kr1, vr0, vr1;
    {   // prologue: tile 0
        long long blk = (long long)g_bt[lb0];
        const float4* kb = (const float4*)(kc + blk * (NHEADS * BLKSZ * HDIM) + headoff);
        const float4* vb = (const float4*)(vc + blk * (NHEADS * BLKSZ * HDIM) + headoff);
        kr0 = kb[tid]; kr1 = kb[tid + 128];
        vr0 = vb[tid]; vr1 = vb[tid + 128];
        ((float4*)(KS[0] + r0 * 68))[c0] = kr0; ((float4*)(KS[0] + r1 * 68))[c1] = kr1;
        ((float4*)(VS[0] + r0 * 68))[c0] = vr0; ((float4*)(VS[0] + r1 * 68))[c1] = vr1;
    }

    float l0 = 0.f, l1 = 0.f;
    ull oxy0 = 0, ozw0 = 0, oxy1 = 0, ozw1 = 0;

    const ulonglong2* q0p = (const ulonglong2*)(QS + grp * 68);
    const ulonglong2* q1p = (const ulonglong2*)(QS + (grp + 8) * 68);

    for (int b = 0; b < BPS; b++) {
        __syncthreads();   // tile b visible; buffer b-1 free
        const int cur = b & 1;

        if (b + 1 < BPS) {  // prefetch tile b+1 into registers
            long long blk = (long long)g_bt[lb0 + b + 1];
            const float4* kb = (const float4*)(kc + blk * (NHEADS * BLKSZ * HDIM) + headoff);
            const float4* vb = (const float4*)(vc + blk * (NHEADS * BLKSZ * HDIM) + headoff);
            kr0 = kb[tid]; kr1 = kb[tid + 128];
            vr0 = vb[tid]; vr1 = vb[tid + 128];
        }

        // ---- scores for (grp,col) and (grp+8,col): packed operands direct from smem
        const ulonglong2* kp = (const ulonglong2*)(KS[cur] + col * 68);
        ull a0 = 0, b0 = 0, a1 = 0, b1 = 0;
#pragma unroll
        for (int i = 0; i < 16; i++) {
            ulonglong2 kk = kp[i];
            ulonglong2 qa = q0p[i];
            ulonglong2 qb = q1p[i];
            a0 = fma2(qa.x, kk.x, a0);
            b0 = fma2(qa.y, kk.y, b0);
            a1 = fma2(qb.x, kk.x, a1);
            b1 = fma2(qb.y, kk.y, b1);
        }
        float x, y, z, w, s0, s1;
        upk2(a0, x, y); upk2(b0, z, w); s0 = (x + y) + (z + w);
        upk2(a1, x, y); upk2(b1, z, w); s1 = (x + y) + (z + w);

        float p0 = __expf(s0), p1 = __expf(s1);
        PS2[grp * 17 + col]       = pk2(p0, p0);
        PS2[(grp + 8) * 17 + col] = pk2(p1, p1);
        float t0 = p0, t1 = p1;
#pragma unroll
        for (int off = 8; off; off >>= 1) {
            t0 += __shfl_xor_sync(0xffffffffu, t0, off);
            t1 += __shfl_xor_sync(0xffffffffu, t1, off);
        }
        l0 += t0; l1 += t1;
        __syncwarp();   // PS2 rows {grp,grp+8} produced & consumed in-warp

        // ---- PV: rows {grp, grp+8}, d-quad col
        const float* vbase = VS[cur];
#pragma unroll
        for (int k2 = 0; k2 < 16; k2++) {
            ulonglong2 v2 = ((const ulonglong2*)(vbase + k2 * 68))[col];
            ull pp0 = PS2[grp * 17 + k2];
            ull pp1 = PS2[(grp + 8) * 17 + k2];
            oxy0 = fma2(pp0, v2.x, oxy0); ozw0 = fma2(pp0, v2.y, ozw0);
            oxy1 = fma2(pp1, v2.x, oxy1); ozw1 = fma2(pp1, v2.y, ozw1);
        }

        if (b + 1 < BPS) {  // stash tile b+1 into the other buffer
            const int nxt = cur ^ 1;
            ((float4*)(KS[nxt] + r0 * 68))[c0] = kr0; ((float4*)(KS[nxt] + r1 * 68))[c1] = kr1;
            ((float4*)(VS[nxt] + r0 * 68))[c0] = vr0; ((float4*)(VS[nxt] + r1 * 68))[c1] = vr1;
        }
    }

    // write unnormalized partials
    float4 o;
    upk2(oxy0, o.x, o.y); upk2(ozw0, o.z, o.w);
    ((float4*)(g_po + ((h * NSPLIT + sp) * QLEN + grp) * HDIM))[col] = o;
    upk2(oxy1, o.x, o.y); upk2(ozw1, o.z, o.w);
    ((float4*)(g_po + ((h * NSPLIT + sp) * QLEN + grp + 8) * HDIM))[col] = o;
    if (col == 0) {
        g_pl[(h * NSPLIT + sp) * QLEN + grp]     = l0;
        g_pl[(h * NSPLIT + sp) * QLEN + grp + 8] = l1;
    }
}

// ---------------------------------------------------------------------------
// Kernel 3: additive combine. grid 128 (h,qi), 1024 threads:
// 16 chunk-threads per d, each sums 8 splits. L by shuffle.
// ---------------------------------------------------------------------------
__global__ __launch_bounds__(1024) void reduce_kernel() {
    int h = blockIdx.x >> 4, qi = blockIdx.x & 15, t = threadIdx.x;
    __shared__ float pacc[16][64];
    __shared__ float lpart[4];

    int d = t & 63, ch = t >> 6;
    float acc = 0.f;
#pragma unroll
    for (int sp = ch * 8; sp < ch * 8 + 8; sp++)
        acc += g_po[((h * NSPLIT + sp) * QLEN + qi) * HDIM + d];
    pacc[ch][d] = acc;

    if (t < NSPLIT) {
        float v = g_pl[(h * NSPLIT + t) * QLEN + qi];
#pragma unroll
        for (int off = 16; off; off >>= 1) v += __shfl_xor_sync(0xffffffffu, v, off);
        if ((t & 31) == 0) lpart[t >> 5] = v;
    }
    __syncthreads();

    if (t < 64) {
        float tot = 0.f;
#pragma unroll
        for (int c = 0; c < 16; c++) tot += pacc[c][t];
        float L = lpart[0] + lpart[1] + lpart[2] + lpart[3];
        g_ao[qi * HIDDEN + h * HDIM + t] = tot / L;
    }
}

// ---------------------------------------------------------------------------
// Kernel 4: out = g_ao @ Wo^T + bo (warp-per-output)
// ---------------------------------------------------------------------------
__global__ __launch_bounds__(256) void oproj_kernel(const float* __restrict__ Wo,
                                                    const float* __restrict__ bo,
                                                    float* __restrict__ out) {
    int gw   = (blockIdx.x * 256 + threadIdx.x) >> 5;
    int lane = threadIdx.x & 31;
    int s = gw >> 9;
    int j = gw & 511;
    const float4* x = (const float4*)(g_ao + s * HIDDEN);
    const float4* w = (const float4*)(Wo + j * HIDDEN);
    float acc = 0.f;
#pragma unroll
    for (int it = 0; it < 4; it++) {
        float4 a = x[lane + it * 32];
        float4 b = w[lane + it * 32];
        acc += a.x * b.x + a.y * b.y + a.z * b.z + a.w * b.w;
    }
#pragma unroll
    for (int off = 16; off; off >>= 1) acc += __shfl_xor_sync(0xffffffffu, acc, off);
    if (lane == 0) out[s * HIDDEN + j] = acc + bo[j];
}

// ---------------------------------------------------------------------------
extern "C" void kernel_launch(void* const* d_in, const int* in_sizes, int n_in,
                              void* d_out, int out_size) {
    const float *hs = 0, *kc = 0, *vc = 0, *Wq = 0, *bq = 0, *Wo = 0, *bo = 0;
    const int* bt_raw = 0;
    for (int i = 0; i < n_in; i++) {
        switch (in_sizes[i]) {
            case QLEN * HIDDEN:                 hs = (const float*)d_in[i]; break;
            case 4096 * NHEADS * BLKSZ * HDIM:
                if (!kc) kc = (const float*)d_in[i];
                else     vc = (const float*)d_in[i];
                break;
            case HIDDEN * HIDDEN:
                if (!Wq) Wq = (const float*)d_in[i];
                else     Wo = (const float*)d_in[i];
                break;
            case HIDDEN:
                if (!bq) bq = (const float*)d_in[i];
                else     bo = (const float*)d_in[i];
                break;
            case NLOGICAL:                      bt_raw = (const int*)d_in[i]; break;
            default: break;
        }
    }
    float* out = (float*)d_out;

    btnorm_kernel<<<1, 1024>>>(bt_raw);
    qproj_kernel<<<1024, 256>>>(hs, Wq, bq);
    dim3 g(NSPLIT, NHEADS);
    attn_kernel<<<g, 128>>>(kc, vc);
    reduce_kernel<<<NHEADS * QLEN, 1024>>>();
    oproj_kernel<<<1024, 256>>>(Wo, bo, out);
}